// round 12
// baseline (speedup 1.0000x reference)
#include <cuda_runtime.h>
#include <cstdint>

#define KN 50000
#define KE 1600000
#define NB 196   // ceil(KN/256) blocks for node-indexed scans
// C=128 channels, H=8 heads, HFD=16

// ---------------- scratch (static __device__ — no allocation allowed) ----------
__device__ __align__(16) float g_emb[KN * 128];   // 25.6 MB, L2-resident during gather
__device__ __align__(16) float g_left[KN * 8];
__device__ __align__(16) float g_right[KN * 8];
__device__ int   g_cnt[KN];        // per-dst edge counts
__device__ int   g_off[KN + 1];    // CSR offsets (exclusive scan, sentinel = KE)
__device__ int   g_cur[KN];        // running cursors for reorder
__device__ int   g_bsum[NB];       // block sums for scan
__device__ int   g_boff[NB];       // block offsets for scan
__device__ int   g_ssrc[KE];       // src ids sorted by dst
__device__ int   g_is64;           // edge_index dtype flag

// ---------------- helpers ------------------------------------------------------
__device__ __forceinline__ float gat_w(float e) {
    e = (e >= 0.f) ? e : 0.2f * e;   // leaky relu(0.2)
    return __expf(e);
}

__device__ __forceinline__ int load_idx(const void* ei, int is64, int pos) {
    if (is64) return (int)((const long long*)ei)[pos];
    return ((const int*)ei)[pos];
}

// packed f32x2 FMA: d = a*b + d  (Blackwell FFMA2 — 2 FLOPs per fma-pipe issue)
__device__ __forceinline__ void ffma2(unsigned long long& d,
                                      unsigned long long a,
                                      unsigned long long b) {
    asm("fma.rn.f32x2 %0, %1, %2, %0;" : "+l"(d) : "l"(a), "l"(b));
}
__device__ __forceinline__ unsigned long long pack2(float lo, float hi) {
    unsigned long long v;
    asm("mov.b64 %0, {%1, %2};" : "=l"(v) : "f"(lo), "f"(hi));
    return v;
}
__device__ __forceinline__ void unpack2(unsigned long long v, float& lo, float& hi) {
    asm("mov.b64 {%0, %1}, %2;" : "=f"(lo), "=f"(hi) : "l"(v));
}

// ---------------- K_d: detect edge_index dtype (1 warp, parallel) --------------
// int64 small non-negative ids => every odd int32 word (high half) is 0.
__global__ void detect_kernel(const int* __restrict__ ei32) {
    int v = ei32[2 * threadIdx.x + 1];
    unsigned nz = __ballot_sync(0xffffffffu, v != 0);
    if (threadIdx.x == 0) g_is64 = (nz == 0u);
}

// ---------------- K_z: zero counters, set CSR sentinel --------------------------
__global__ void zero_kernel() {
    int i = blockIdx.x * blockDim.x + threadIdx.x;
    if (i < KN) g_cnt[i] = 0;
    if (i == 0) g_off[KN] = KE;
}

// ---------------- K1: emb = X @ W^T ; left/right = head-dots -------------------
// 64 nodes/block, 8 warps, 8 nodes/warp; lane t owns channels 4t..4t+3.
// Inner product done on the packed f32x2 pipe (FFMA2).
__global__ __launch_bounds__(256) void gemm_kernel(
    const float* __restrict__ x, const float* __restrict__ W,
    const float* __restrict__ aL, const float* __restrict__ aR)
{
    __shared__ __align__(16) float  sW[32 * 132];  // W chunk transposed [kk][c], pad 132
    __shared__ __align__(16) float2 sX2[64 * 32];  // x chunk [j][kk], value duplicated

    const int tid  = threadIdx.x;
    const int lane = tid & 31;
    const int warp = tid >> 5;
    const int n0   = blockIdx.x * 64;

    unsigned long long acc2[8][2];
#pragma unroll
    for (int j = 0; j < 8; j++) { acc2[j][0] = 0ull; acc2[j][1] = 0ull; }

#pragma unroll 1
    for (int k0 = 0; k0 < 128; k0 += 32) {
        // stage W chunk, transposed: sW[kk][c] = W[c*128 + k0+kk]  (coalesced)
#pragma unroll
        for (int i = 0; i < 16; i++) {
            int idx = tid + i * 256;          // 0..4095
            int c   = idx >> 5;
            int kk  = idx & 31;
            sW[kk * 132 + c] = W[c * 128 + k0 + kk];
        }
        // stage x chunk duplicated: sX2[j][kk] = (v, v) — packed broadcast source
#pragma unroll
        for (int i = 0; i < 8; i++) {
            int idx = tid + i * 256;          // 0..2047
            int j   = idx >> 5;
            int kk  = idx & 31;
            int n   = n0 + j;
            float v = (n < KN) ? x[n * 128 + k0 + kk] : 0.f;
            sX2[j * 32 + kk] = make_float2(v, v);
        }
        __syncthreads();

        const int jb = warp * 8;
#pragma unroll
        for (int kk = 0; kk < 32; kk++) {
            float4 wv = *(const float4*)&sW[kk * 132 + lane * 4];
            unsigned long long wlo = pack2(wv.x, wv.y);
            unsigned long long whi = pack2(wv.z, wv.w);
#pragma unroll
            for (int j = 0; j < 8; j++) {
                unsigned long long xv =
                    *(const unsigned long long*)&sX2[(jb + j) * 32 + kk];  // smem bcast
                ffma2(acc2[j][0], xv, wlo);
                ffma2(acc2[j][1], xv, whi);
            }
        }
        __syncthreads();
    }

    // epilogue: unpack, store emb rows; left/right via a-dot + 4-lane shfl reduce
    const int h   = lane >> 2;
    const int ci0 = (lane * 4) & 15;
#pragma unroll
    for (int j = 0; j < 8; j++) {
        int n = n0 + warp * 8 + j;
        if (n >= KN) break;               // uniform across warp
        float4 acc;
        unpack2(acc2[j][0], acc.x, acc.y);
        unpack2(acc2[j][1], acc.z, acc.w);
        *(float4*)&g_emb[n * 128 + lane * 4] = acc;

        float pl = acc.x * aL[(ci0 + 0) * 8 + h] + acc.y * aL[(ci0 + 1) * 8 + h]
                 + acc.z * aL[(ci0 + 2) * 8 + h] + acc.w * aL[(ci0 + 3) * 8 + h];
        float pr = acc.x * aR[(ci0 + 0) * 8 + h] + acc.y * aR[(ci0 + 1) * 8 + h]
                 + acc.z * aR[(ci0 + 2) * 8 + h] + acc.w * aR[(ci0 + 3) * 8 + h];
        pl += __shfl_xor_sync(0xffffffffu, pl, 1);
        pl += __shfl_xor_sync(0xffffffffu, pl, 2);
        pr += __shfl_xor_sync(0xffffffffu, pr, 1);
        pr += __shfl_xor_sync(0xffffffffu, pr, 2);
        if ((lane & 3) == 0) {
            g_left[n * 8 + h]  = pl;
            g_right[n * 8 + h] = pr;
        }
    }
}

// ---------------- K2: histogram of dst -----------------------------------------
__global__ __launch_bounds__(256) void hist_kernel(const void* __restrict__ ei) {
    int e = blockIdx.x * 256 + threadIdx.x;
    if (e >= KE) return;
    int dst = load_idx(ei, g_is64, KE + e);
    atomicAdd(&g_cnt[dst], 1);
}

// ---------------- K3a/b/c: exclusive scan over g_cnt (3-kernel block scan) -----
__global__ void scan1_kernel() {   // block sums
    __shared__ int s[256];
    int tid = threadIdx.x;
    int i   = blockIdx.x * 256 + tid;
    s[tid] = (i < KN) ? g_cnt[i] : 0;
    __syncthreads();
    for (int st = 128; st > 0; st >>= 1) {
        if (tid < st) s[tid] += s[tid + st];
        __syncthreads();
    }
    if (tid == 0) g_bsum[blockIdx.x] = s[0];
}

__global__ void scan2_kernel() {   // exclusive scan of NB block sums (1 block)
    __shared__ int s[256];
    int tid = threadIdx.x;
    int v = (tid < NB) ? g_bsum[tid] : 0;
    s[tid] = v;
    __syncthreads();
    for (int st = 1; st < 256; st <<= 1) {
        int t = (tid >= st) ? s[tid - st] : 0;
        __syncthreads();
        s[tid] += t;
        __syncthreads();
    }
    if (tid < NB) g_boff[tid] = s[tid] - v;   // exclusive
}

__global__ void scan3_kernel() {   // in-block exclusive scan + block offset
    __shared__ int s[256];
    int tid = threadIdx.x;
    int i   = blockIdx.x * 256 + tid;
    int v = (i < KN) ? g_cnt[i] : 0;
    s[tid] = v;
    __syncthreads();
    for (int st = 1; st < 256; st <<= 1) {
        int t = (tid >= st) ? s[tid - st] : 0;
        __syncthreads();
        s[tid] += t;
        __syncthreads();
    }
    if (i < KN) {
        int excl = s[tid] - v + g_boff[blockIdx.x];
        g_off[i] = excl;
        g_cur[i] = excl;
    }
}

// ---------------- K4: reorder src ids into dst-sorted order --------------------
__global__ __launch_bounds__(256) void reorder_kernel(const void* __restrict__ ei) {
    int e = blockIdx.x * 256 + threadIdx.x;
    if (e >= KE) return;
    const int is64 = g_is64;
    int src = load_idx(ei, is64, e);
    int dst = load_idx(ei, is64, KE + e);
    int pos = atomicAdd(&g_cur[dst], 1);
    g_ssrc[pos] = src;
}

// ---------------- K5: warp-per-dst gather: out = (Σ w·emb[src])/Σw + bias ------
__global__ __launch_bounds__(256) void gather_kernel(
    float* __restrict__ out, const float* __restrict__ bias)
{
    const int dst  = (blockIdx.x * 256 + threadIdx.x) >> 5;
    const int lane = threadIdx.x & 31;
    if (dst >= KN) return;

    const int h  = lane >> 2;      // this lane's head
    const int c4 = lane * 4;       // channel group

    const int beg = g_off[dst];
    const int end = g_off[dst + 1];
    const float rh = g_right[dst * 8 + h];

    float4 acc = make_float4(0.f, 0.f, 0.f, 0.f);
    float  wsum = 0.f;

    for (int base = beg; base < end; base += 32) {
        int n = end - base; if (n > 32) n = 32;
        int mysrc = (lane < n) ? g_ssrc[base + lane] : 0;
#pragma unroll 4
        for (int j = 0; j < n; j++) {
            int src = __shfl_sync(0xffffffffu, mysrc, j);
            float w = gat_w(g_left[src * 8 + h] + rh);
            wsum += w;
            float4 v = *(const float4*)&g_emb[src * 128 + c4];
            acc.x += w * v.x;
            acc.y += w * v.y;
            acc.z += w * v.z;
            acc.w += w * v.w;
        }
    }

    float inv = (end > beg) ? __fdividef(1.f, wsum) : 0.f;
    float4 b = *(const float4*)&bias[c4];
    float4 o;
    o.x = acc.x * inv + b.x;
    o.y = acc.y * inv + b.y;
    o.z = acc.z * inv + b.z;
    o.w = acc.w * inv + b.w;
    *(float4*)&out[dst * 128 + c4] = o;
}

// ---------------- launch -------------------------------------------------------
extern "C" void kernel_launch(void* const* d_in, const int* in_sizes, int n_in,
                              void* d_out, int out_size)
{
    // Bind inputs by element count (robust to metadata ordering):
    //   node_feats: 6,400,000   edge_index: 3,200,000   W: 16,384
    //   a_left / a_right / bias: 128 each (relative dict order preserved)
    const float* x    = nullptr;
    const void*  ei   = nullptr;
    const float* W    = nullptr;
    const float* p128[3] = {nullptr, nullptr, nullptr};
    int n128 = 0;
    for (int i = 0; i < n_in; i++) {
        long long sz = in_sizes[i];
        if      (sz == (long long)KN * 128) x  = (const float*)d_in[i];
        else if (sz == (long long)KE * 2)   ei = d_in[i];
        else if (sz == 128 * 128)           W  = (const float*)d_in[i];
        else if (sz == 128 && n128 < 3)     p128[n128++] = (const float*)d_in[i];
    }
    const float* aL   = p128[0];
    const float* aR   = p128[1];
    const float* bias = p128[2];
    float* out = (float*)d_out;
    (void)out_size;

    detect_kernel<<<1, 32>>>((const int*)ei);
    zero_kernel<<<NB, 256>>>();
    hist_kernel<<<(KE + 255) / 256, 256>>>(ei);
    gemm_kernel<<<(KN + 63) / 64, 256>>>(x, W, aL, aR);
    scan1_kernel<<<NB, 256>>>();
    scan2_kernel<<<1, 256>>>();
    scan3_kernel<<<NB, 256>>>();
    reorder_kernel<<<(KE + 255) / 256, 256>>>(ei);
    gather_kernel<<<(KN * 32 + 255) / 256, 256>>>(out, bias);
}

// round 14
// speedup vs baseline: 1.0357x; 1.0357x over previous
#include <cuda_runtime.h>
#include <cstdint>

#define KN 50000
#define KE 1600000
#define NB 196   // ceil(KN/256) blocks for node-indexed scans
// C=128 channels, H=8 heads, HFD=16

// ---------------- scratch (static __device__ — no allocation allowed) ----------
__device__ __align__(16) float g_emb[KN * 128];   // 25.6 MB, L2-resident during gather
__device__ __align__(16) float g_left[KN * 8];
__device__ __align__(16) float g_right[KN * 8];
__device__ int   g_cnt[KN];        // per-dst edge counts
__device__ int   g_off[KN + 1];    // CSR offsets (exclusive scan, sentinel = KE)
__device__ int   g_cur[KN];        // running cursors for reorder
__device__ int   g_bsum[NB];       // block sums for scan
__device__ int   g_boff[NB];       // block offsets for scan
__device__ int   g_ssrc[KE];       // src ids sorted by dst
__device__ int   g_is64;           // edge_index dtype flag

// ---------------- helpers ------------------------------------------------------
__device__ __forceinline__ float gat_w(float e) {
    e = (e >= 0.f) ? e : 0.2f * e;   // leaky relu(0.2)
    return __expf(e);
}

__device__ __forceinline__ int load_idx(const void* ei, int is64, int pos) {
    if (is64) return (int)((const long long*)ei)[pos];
    return ((const int*)ei)[pos];
}

// packed f32x2 FMA: d = a*b + d  (Blackwell FFMA2 — 2 FLOPs per fma-pipe issue)
__device__ __forceinline__ void ffma2(unsigned long long& d,
                                      unsigned long long a,
                                      unsigned long long b) {
    asm("fma.rn.f32x2 %0, %1, %2, %0;" : "+l"(d) : "l"(a), "l"(b));
}
__device__ __forceinline__ unsigned long long pack2(float lo, float hi) {
    unsigned long long v;
    asm("mov.b64 %0, {%1, %2};" : "=l"(v) : "f"(lo), "f"(hi));
    return v;
}
__device__ __forceinline__ void unpack2(unsigned long long v, float& lo, float& hi) {
    asm("mov.b64 {%0, %1}, %2;" : "=f"(lo), "=f"(hi) : "l"(v));
}

// ---------------- K_d: detect edge_index dtype (1 warp, parallel) --------------
// int64 small non-negative ids => every odd int32 word (high half) is 0.
__global__ void detect_kernel(const int* __restrict__ ei32) {
    int v = ei32[2 * threadIdx.x + 1];
    unsigned nz = __ballot_sync(0xffffffffu, v != 0);
    if (threadIdx.x == 0) g_is64 = (nz == 0u);
}

// ---------------- K_z: zero counters, set CSR sentinel --------------------------
__global__ void zero_kernel() {
    int i = blockIdx.x * blockDim.x + threadIdx.x;
    if (i < KN) g_cnt[i] = 0;
    if (i == 0) g_off[KN] = KE;
}

// ---------------- K1: emb = X @ W^T ; left/right = head-dots -------------------
// 64 nodes/block, 8 warps, 8 nodes/warp; lane t owns channels 4t..4t+3.
// Inner product done on the packed f32x2 pipe (FFMA2).
__global__ __launch_bounds__(256) void gemm_kernel(
    const float* __restrict__ x, const float* __restrict__ W,
    const float* __restrict__ aL, const float* __restrict__ aR)
{
    __shared__ __align__(16) float  sW[32 * 132];  // W chunk transposed [kk][c], pad 132
    __shared__ __align__(16) float2 sX2[64 * 32];  // x chunk [j][kk], value duplicated

    const int tid  = threadIdx.x;
    const int lane = tid & 31;
    const int warp = tid >> 5;
    const int n0   = blockIdx.x * 64;

    unsigned long long acc2[8][2];
#pragma unroll
    for (int j = 0; j < 8; j++) { acc2[j][0] = 0ull; acc2[j][1] = 0ull; }

#pragma unroll 1
    for (int k0 = 0; k0 < 128; k0 += 32) {
        // stage W chunk, transposed: sW[kk][c] = W[c*128 + k0+kk]  (coalesced)
#pragma unroll
        for (int i = 0; i < 16; i++) {
            int idx = tid + i * 256;          // 0..4095
            int c   = idx >> 5;
            int kk  = idx & 31;
            sW[kk * 132 + c] = W[c * 128 + k0 + kk];
        }
        // stage x chunk duplicated: sX2[j][kk] = (v, v) — packed broadcast source
#pragma unroll
        for (int i = 0; i < 8; i++) {
            int idx = tid + i * 256;          // 0..2047
            int j   = idx >> 5;
            int kk  = idx & 31;
            int n   = n0 + j;
            float v = (n < KN) ? x[n * 128 + k0 + kk] : 0.f;
            sX2[j * 32 + kk] = make_float2(v, v);
        }
        __syncthreads();

        const int jb = warp * 8;
#pragma unroll
        for (int kk = 0; kk < 32; kk++) {
            float4 wv = *(const float4*)&sW[kk * 132 + lane * 4];
            unsigned long long wlo = pack2(wv.x, wv.y);
            unsigned long long whi = pack2(wv.z, wv.w);
#pragma unroll
            for (int j = 0; j < 8; j++) {
                unsigned long long xv =
                    *(const unsigned long long*)&sX2[(jb + j) * 32 + kk];  // smem bcast
                ffma2(acc2[j][0], xv, wlo);
                ffma2(acc2[j][1], xv, whi);
            }
        }
        __syncthreads();
    }

    // epilogue: unpack, store emb rows; left/right via a-dot + 4-lane shfl reduce
    const int h   = lane >> 2;
    const int ci0 = (lane * 4) & 15;
#pragma unroll
    for (int j = 0; j < 8; j++) {
        int n = n0 + warp * 8 + j;
        if (n >= KN) break;               // uniform across warp
        float4 acc;
        unpack2(acc2[j][0], acc.x, acc.y);
        unpack2(acc2[j][1], acc.z, acc.w);
        *(float4*)&g_emb[n * 128 + lane * 4] = acc;

        float pl = acc.x * aL[(ci0 + 0) * 8 + h] + acc.y * aL[(ci0 + 1) * 8 + h]
                 + acc.z * aL[(ci0 + 2) * 8 + h] + acc.w * aL[(ci0 + 3) * 8 + h];
        float pr = acc.x * aR[(ci0 + 0) * 8 + h] + acc.y * aR[(ci0 + 1) * 8 + h]
                 + acc.z * aR[(ci0 + 2) * 8 + h] + acc.w * aR[(ci0 + 3) * 8 + h];
        pl += __shfl_xor_sync(0xffffffffu, pl, 1);
        pl += __shfl_xor_sync(0xffffffffu, pl, 2);
        pr += __shfl_xor_sync(0xffffffffu, pr, 1);
        pr += __shfl_xor_sync(0xffffffffu, pr, 2);
        if ((lane & 3) == 0) {
            g_left[n * 8 + h]  = pl;
            g_right[n * 8 + h] = pr;
        }
    }
}

// ---------------- K2: histogram of dst -----------------------------------------
__global__ __launch_bounds__(256) void hist_kernel(const void* __restrict__ ei) {
    int e = blockIdx.x * 256 + threadIdx.x;
    if (e >= KE) return;
    int dst = load_idx(ei, g_is64, KE + e);
    atomicAdd(&g_cnt[dst], 1);
}

// ---------------- K3a/b/c: exclusive scan over g_cnt (3-kernel block scan) -----
__global__ void scan1_kernel() {   // block sums
    __shared__ int s[256];
    int tid = threadIdx.x;
    int i   = blockIdx.x * 256 + tid;
    s[tid] = (i < KN) ? g_cnt[i] : 0;
    __syncthreads();
    for (int st = 128; st > 0; st >>= 1) {
        if (tid < st) s[tid] += s[tid + st];
        __syncthreads();
    }
    if (tid == 0) g_bsum[blockIdx.x] = s[0];
}

__global__ void scan2_kernel() {   // exclusive scan of NB block sums (1 block)
    __shared__ int s[256];
    int tid = threadIdx.x;
    int v = (tid < NB) ? g_bsum[tid] : 0;
    s[tid] = v;
    __syncthreads();
    for (int st = 1; st < 256; st <<= 1) {
        int t = (tid >= st) ? s[tid - st] : 0;
        __syncthreads();
        s[tid] += t;
        __syncthreads();
    }
    if (tid < NB) g_boff[tid] = s[tid] - v;   // exclusive
}

__global__ void scan3_kernel() {   // in-block exclusive scan + block offset
    __shared__ int s[256];
    int tid = threadIdx.x;
    int i   = blockIdx.x * 256 + tid;
    int v = (i < KN) ? g_cnt[i] : 0;
    s[tid] = v;
    __syncthreads();
    for (int st = 1; st < 256; st <<= 1) {
        int t = (tid >= st) ? s[tid - st] : 0;
        __syncthreads();
        s[tid] += t;
        __syncthreads();
    }
    if (i < KN) {
        int excl = s[tid] - v + g_boff[blockIdx.x];
        g_off[i] = excl;
        g_cur[i] = excl;
    }
}

// ---------------- K4: reorder src ids into dst-sorted order --------------------
__global__ __launch_bounds__(256) void reorder_kernel(const void* __restrict__ ei) {
    int e = blockIdx.x * 256 + threadIdx.x;
    if (e >= KE) return;
    const int is64 = g_is64;
    int src = load_idx(ei, is64, e);
    int dst = load_idx(ei, is64, KE + e);
    int pos = atomicAdd(&g_cur[dst], 1);
    g_ssrc[pos] = src;
}

// ---------------- K5: warp-per-dst gather: out = (Σ w·emb[src])/Σw + bias ------
__global__ __launch_bounds__(256) void gather_kernel(
    float* __restrict__ out, const float* __restrict__ bias)
{
    const int dst  = (blockIdx.x * 256 + threadIdx.x) >> 5;
    const int lane = threadIdx.x & 31;
    if (dst >= KN) return;

    const int h  = lane >> 2;      // this lane's head
    const int c4 = lane * 4;       // channel group

    const int beg = g_off[dst];
    const int end = g_off[dst + 1];
    const float rh = g_right[dst * 8 + h];

    float4 acc = make_float4(0.f, 0.f, 0.f, 0.f);
    float  wsum = 0.f;

    for (int base = beg; base < end; base += 32) {
        int n = end - base; if (n > 32) n = 32;
        int mysrc = (lane < n) ? g_ssrc[base + lane] : 0;
#pragma unroll 4
        for (int j = 0; j < n; j++) {
            int src = __shfl_sync(0xffffffffu, mysrc, j);
            float w = gat_w(g_left[src * 8 + h] + rh);
            wsum += w;
            float4 v = *(const float4*)&g_emb[src * 128 + c4];
            acc.x += w * v.x;
            acc.y += w * v.y;
            acc.z += w * v.z;
            acc.w += w * v.w;
        }
    }

    float inv = (end > beg) ? __fdividef(1.f, wsum) : 0.f;
    float4 b = *(const float4*)&bias[c4];
    float4 o;
    o.x = acc.x * inv + b.x;
    o.y = acc.y * inv + b.y;
    o.z = acc.z * inv + b.z;
    o.w = acc.w * inv + b.w;
    *(float4*)&out[dst * 128 + c4] = o;
}

// ---------------- launch -------------------------------------------------------
extern "C" void kernel_launch(void* const* d_in, const int* in_sizes, int n_in,
                              void* d_out, int out_size)
{
    // Bind inputs by element count (robust to metadata ordering):
    //   node_feats: 6,400,000   edge_index: 3,200,000   W: 16,384
    //   a_left / a_right / bias: 128 each (relative dict order preserved)
    const float* x    = nullptr;
    const void*  ei   = nullptr;
    const float* W    = nullptr;
    const float* p128[3] = {nullptr, nullptr, nullptr};
    int n128 = 0;
    for (int i = 0; i < n_in; i++) {
        long long sz = in_sizes[i];
        if      (sz == (long long)KN * 128) x  = (const float*)d_in[i];
        else if (sz == (long long)KE * 2)   ei = d_in[i];
        else if (sz == 128 * 128)           W  = (const float*)d_in[i];
        else if (sz == 128 && n128 < 3)     p128[n128++] = (const float*)d_in[i];
    }
    const float* aL   = p128[0];
    const float* aR   = p128[1];
    const float* bias = p128[2];
    float* out = (float*)d_out;
    (void)out_size;

    detect_kernel<<<1, 32>>>((const int*)ei);
    zero_kernel<<<NB, 256>>>();
    hist_kernel<<<(KE + 255) / 256, 256>>>(ei);
    gemm_kernel<<<(KN + 63) / 64, 256>>>(x, W, aL, aR);
    scan1_kernel<<<NB, 256>>>();
    scan2_kernel<<<1, 256>>>();
    scan3_kernel<<<NB, 256>>>();
    reorder_kernel<<<(KE + 255) / 256, 256>>>(ei);
    gather_kernel<<<(KN * 32 + 255) / 256, 256>>>(out, bias);
}

// round 17
// speedup vs baseline: 1.0862x; 1.0487x over previous
#include <cuda_runtime.h>
#include <cuda_fp16.h>
#include <cstdint>

#define KN 50000
#define KE 1600000
#define NB 196   // ceil(KN/256) blocks for node-indexed scans
// C=128 channels, H=8 heads, HFD=16

// ---------------- scratch (static __device__ — no allocation allowed) ----------
__device__ __align__(16) __half g_embh[KN * 128];  // 12.8 MB, L2-resident (fp16!)
__device__ __align__(16) float g_left[KN * 8];
__device__ __align__(16) float g_right[KN * 8];
__device__ int   g_cnt[KN];        // per-dst edge counts
__device__ int   g_off[KN + 1];    // CSR offsets (exclusive scan, sentinel = KE)
__device__ int   g_cur[KN];        // running cursors for reorder
__device__ int   g_bsum[NB];       // block sums for scan
__device__ int   g_boff[NB];       // block offsets for scan
__device__ int   g_ssrc[KE];       // src ids sorted by dst
__device__ int   g_is64;           // edge_index dtype flag

// ---------------- helpers ------------------------------------------------------
__device__ __forceinline__ float gat_w(float e) {
    e = (e >= 0.f) ? e : 0.2f * e;   // leaky relu(0.2)
    return __expf(e);
}

__device__ __forceinline__ int load_idx(const void* ei, int is64, int pos) {
    if (is64) return (int)((const long long*)ei)[pos];
    return ((const int*)ei)[pos];
}

// ---------------- K_d: detect edge_index dtype (1 warp, parallel) --------------
// int64 small non-negative ids => every odd int32 word (high half) is 0.
__global__ void detect_kernel(const int* __restrict__ ei32) {
    int v = ei32[2 * threadIdx.x + 1];
    unsigned nz = __ballot_sync(0xffffffffu, v != 0);
    if (threadIdx.x == 0) g_is64 = (nz == 0u);
}

// ---------------- K_z: zero counters, set CSR sentinel --------------------------
__global__ void zero_kernel() {
    int i = blockIdx.x * blockDim.x + threadIdx.x;
    if (i < KN) g_cnt[i] = 0;
    if (i == 0) g_off[KN] = KE;
}

// ---------------- K1: emb = X @ W^T ; left/right = head-dots -------------------
// (R9 scalar-FFMA version — measured at 92% of the FFMA roofline.)
// 64 nodes/block, 8 warps, 8 nodes/warp; lane t owns channels 4t..4t+3.
// Epilogue stores emb in fp16 (halves gather traffic, eps 4.9e-4); logits fp32.
__global__ __launch_bounds__(256) void gemm_kernel(
    const float* __restrict__ x, const float* __restrict__ W,
    const float* __restrict__ aL, const float* __restrict__ aR)
{
    __shared__ __align__(16) float sW[32 * 132];  // W chunk transposed [kk][c], pad 132
    __shared__ float sX[64 * 32];                 // x chunk [j][kk]

    const int tid  = threadIdx.x;
    const int lane = tid & 31;
    const int warp = tid >> 5;
    const int n0   = blockIdx.x * 64;

    float4 acc[8];
#pragma unroll
    for (int j = 0; j < 8; j++) acc[j] = make_float4(0.f, 0.f, 0.f, 0.f);

#pragma unroll 1
    for (int k0 = 0; k0 < 128; k0 += 32) {
#pragma unroll
        for (int i = 0; i < 16; i++) {
            int idx = tid + i * 256;
            int c   = idx >> 5;
            int kk  = idx & 31;
            sW[kk * 132 + c] = W[c * 128 + k0 + kk];
        }
#pragma unroll
        for (int i = 0; i < 8; i++) {
            int idx = tid + i * 256;
            int j   = idx >> 5;
            int kk  = idx & 31;
            int n   = n0 + j;
            sX[j * 32 + kk] = (n < KN) ? x[n * 128 + k0 + kk] : 0.f;
        }
        __syncthreads();

        const int jb = warp * 8;
#pragma unroll
        for (int kk = 0; kk < 32; kk++) {
            float4 wv = *(const float4*)&sW[kk * 132 + lane * 4];
#pragma unroll
            for (int j = 0; j < 8; j++) {
                float xv = sX[(jb + j) * 32 + kk];   // smem broadcast
                acc[j].x += xv * wv.x;
                acc[j].y += xv * wv.y;
                acc[j].z += xv * wv.z;
                acc[j].w += xv * wv.w;
            }
        }
        __syncthreads();
    }

    const int h   = lane >> 2;
    const int ci0 = (lane * 4) & 15;
#pragma unroll
    for (int j = 0; j < 8; j++) {
        int n = n0 + warp * 8 + j;
        if (n >= KN) break;               // uniform across warp
        // fp16 emb store (message payload); fp32 kept in regs for logits below
        __half2 h0 = __float22half2_rn(make_float2(acc[j].x, acc[j].y));
        __half2 h1 = __float22half2_rn(make_float2(acc[j].z, acc[j].w));
        uint2 packed;
        packed.x = *(unsigned*)&h0;
        packed.y = *(unsigned*)&h1;
        *(uint2*)&g_embh[n * 128 + lane * 4] = packed;

        float pl = acc[j].x * aL[(ci0 + 0) * 8 + h] + acc[j].y * aL[(ci0 + 1) * 8 + h]
                 + acc[j].z * aL[(ci0 + 2) * 8 + h] + acc[j].w * aL[(ci0 + 3) * 8 + h];
        float pr = acc[j].x * aR[(ci0 + 0) * 8 + h] + acc[j].y * aR[(ci0 + 1) * 8 + h]
                 + acc[j].z * aR[(ci0 + 2) * 8 + h] + acc[j].w * aR[(ci0 + 3) * 8 + h];
        pl += __shfl_xor_sync(0xffffffffu, pl, 1);
        pl += __shfl_xor_sync(0xffffffffu, pl, 2);
        pr += __shfl_xor_sync(0xffffffffu, pr, 1);
        pr += __shfl_xor_sync(0xffffffffu, pr, 2);
        if ((lane & 3) == 0) {
            g_left[n * 8 + h]  = pl;
            g_right[n * 8 + h] = pr;
        }
    }
}

// ---------------- K2: histogram of dst -----------------------------------------
__global__ __launch_bounds__(256) void hist_kernel(const void* __restrict__ ei) {
    int e = blockIdx.x * 256 + threadIdx.x;
    if (e >= KE) return;
    int dst = load_idx(ei, g_is64, KE + e);
    atomicAdd(&g_cnt[dst], 1);
}

// ---------------- K3a/b/c: exclusive scan over g_cnt (3-kernel block scan) -----
__global__ void scan1_kernel() {   // block sums
    __shared__ int s[256];
    int tid = threadIdx.x;
    int i   = blockIdx.x * 256 + tid;
    s[tid] = (i < KN) ? g_cnt[i] : 0;
    __syncthreads();
    for (int st = 128; st > 0; st >>= 1) {
        if (tid < st) s[tid] += s[tid + st];
        __syncthreads();
    }
    if (tid == 0) g_bsum[blockIdx.x] = s[0];
}

__global__ void scan2_kernel() {   // exclusive scan of NB block sums (1 block)
    __shared__ int s[256];
    int tid = threadIdx.x;
    int v = (tid < NB) ? g_bsum[tid] : 0;
    s[tid] = v;
    __syncthreads();
    for (int st = 1; st < 256; st <<= 1) {
        int t = (tid >= st) ? s[tid - st] : 0;
        __syncthreads();
        s[tid] += t;
        __syncthreads();
    }
    if (tid < NB) g_boff[tid] = s[tid] - v;   // exclusive
}

__global__ void scan3_kernel() {   // in-block exclusive scan + block offset
    __shared__ int s[256];
    int tid = threadIdx.x;
    int i   = blockIdx.x * 256 + tid;
    int v = (i < KN) ? g_cnt[i] : 0;
    s[tid] = v;
    __syncthreads();
    for (int st = 1; st < 256; st <<= 1) {
        int t = (tid >= st) ? s[tid - st] : 0;
        __syncthreads();
        s[tid] += t;
        __syncthreads();
    }
    if (i < KN) {
        int excl = s[tid] - v + g_boff[blockIdx.x];
        g_off[i] = excl;
        g_cur[i] = excl;
    }
}

// ---------------- K4: reorder src ids into dst-sorted order --------------------
__global__ __launch_bounds__(256) void reorder_kernel(const void* __restrict__ ei) {
    int e = blockIdx.x * 256 + threadIdx.x;
    if (e >= KE) return;
    const int is64 = g_is64;
    int src = load_idx(ei, is64, e);
    int dst = load_idx(ei, is64, KE + e);
    int pos = atomicAdd(&g_cur[dst], 1);
    g_ssrc[pos] = src;
}

// ---------------- K5: warp-per-dst gather: out = (Σ w·emb[src])/Σw + bias ------
// emb rows are fp16 (8 bytes/lane); accumulation in fp32.
__global__ __launch_bounds__(256) void gather_kernel(
    float* __restrict__ out, const float* __restrict__ bias)
{
    const int dst  = (blockIdx.x * 256 + threadIdx.x) >> 5;
    const int lane = threadIdx.x & 31;
    if (dst >= KN) return;

    const int h  = lane >> 2;      // this lane's head
    const int c4 = lane * 4;       // channel group

    const int beg = g_off[dst];
    const int end = g_off[dst + 1];
    const float rh = g_right[dst * 8 + h];

    float4 acc = make_float4(0.f, 0.f, 0.f, 0.f);
    float  wsum = 0.f;

    for (int base = beg; base < end; base += 32) {
        int n = end - base; if (n > 32) n = 32;
        int mysrc = (lane < n) ? g_ssrc[base + lane] : 0;
#pragma unroll 4
        for (int j = 0; j < n; j++) {
            int src = __shfl_sync(0xffffffffu, mysrc, j);
            float w = gat_w(g_left[src * 8 + h] + rh);
            wsum += w;
            uint2 raw = *(const uint2*)&g_embh[src * 128 + c4];
            float2 v0 = __half22float2(*(__half2*)&raw.x);
            float2 v1 = __half22float2(*(__half2*)&raw.y);
            acc.x += w * v0.x;
            acc.y += w * v0.y;
            acc.z += w * v1.x;
            acc.w += w * v1.y;
        }
    }

    float inv = (end > beg) ? __fdividef(1.f, wsum) : 0.f;
    float4 b = *(const float4*)&bias[c4];
    float4 o;
    o.x = acc.x * inv + b.x;
    o.y = acc.y * inv + b.y;
    o.z = acc.z * inv + b.z;
    o.w = acc.w * inv + b.w;
    *(float4*)&out[dst * 128 + c4] = o;
}

// ---------------- launch -------------------------------------------------------
extern "C" void kernel_launch(void* const* d_in, const int* in_sizes, int n_in,
                              void* d_out, int out_size)
{
    // Bind inputs by element count (robust to metadata ordering):
    //   node_feats: 6,400,000   edge_index: 3,200,000   W: 16,384
    //   a_left / a_right / bias: 128 each (relative dict order preserved)
    const float* x    = nullptr;
    const void*  ei   = nullptr;
    const float* W    = nullptr;
    const float* p128[3] = {nullptr, nullptr, nullptr};
    int n128 = 0;
    for (int i = 0; i < n_in; i++) {
        long long sz = in_sizes[i];
        if      (sz == (long long)KN * 128) x  = (const float*)d_in[i];
        else if (sz == (long long)KE * 2)   ei = d_in[i];
        else if (sz == 128 * 128)           W  = (const float*)d_in[i];
        else if (sz == 128 && n128 < 3)     p128[n128++] = (const float*)d_in[i];
    }
    const float* aL   = p128[0];
    const float* aR   = p128[1];
    const float* bias = p128[2];
    float* out = (float*)d_out;
    (void)out_size;

    detect_kernel<<<1, 32>>>((const int*)ei);
    zero_kernel<<<NB, 256>>>();
    hist_kernel<<<(KE + 255) / 256, 256>>>(ei);
    gemm_kernel<<<(KN + 63) / 64, 256>>>(x, W, aL, aR);
    scan1_kernel<<<NB, 256>>>();
    scan2_kernel<<<1, 256>>>();
    scan3_kernel<<<NB, 256>>>();
    reorder_kernel<<<(KE + 255) / 256, 256>>>(ei);
    gather_kernel<<<(KN * 32 + 255) / 256, 256>>>(out, bias);
}